// round 9
// baseline (speedup 1.0000x reference)
#include <cuda_runtime.h>
#include <cuda_fp16.h>
#include <cstdint>

// Shapes fixed by dataset: B=64, E=16, D=64, Q_DIM=64 -> K=128.
#define B_DIM    64
#define K_DIM    128
#define NTILE    32            // W/U rows per tile
#define THREADS  256
#define HIST_CAP 262144
#define PITCH    136           // halves per row (272B): ldsm conflict-free
#define ABUF     17408         // Ah+Al per buffer (2 x 8704)
#define AL_DELTA 8704

// SMEM layout (bytes)
#define OFF_XH   0             // 64 x 136 halves = 17408
#define OFF_XL   17408
#define OFF_A    34816         // [Ah0, Al0, Ah1, Al1] = 2 x 17408
#define OFF_COLS 69632         // 2 x 32 ints = 256
#define SMEM_TOTAL 69888

__device__ __half g_Xh[B_DIM * K_DIM];
__device__ __half g_Xl[B_DIM * K_DIM];
__device__ float  g_hist[HIST_CAP];

// ---------------------------------------------------------------------------
__device__ __forceinline__ uint32_t smem_u32(const void* p) {
    uint32_t a;
    asm("{ .reg .u64 t; cvta.to.shared.u64 t, %1; cvt.u32.u64 %0, t; }"
        : "=r"(a) : "l"(p));
    return a;
}

__device__ __forceinline__ uint32_t packh(float lo, float hi) {
    uint32_t r;
    asm("cvt.rn.f16x2.f32 %0, %1, %2;" : "=r"(r) : "f"(hi), "f"(lo));
    return r;
}

__device__ __forceinline__ void mma16816(float* d, const uint32_t* a,
                                         uint32_t b0, uint32_t b1) {
    asm volatile(
        "mma.sync.aligned.m16n8k16.row.col.f32.f16.f16.f32 "
        "{%0,%1,%2,%3}, {%4,%5,%6,%7}, {%8,%9}, {%0,%1,%2,%3};"
        : "+f"(d[0]), "+f"(d[1]), "+f"(d[2]), "+f"(d[3])
        : "r"(a[0]), "r"(a[1]), "r"(a[2]), "r"(a[3]), "r"(b0), "r"(b1));
}

__device__ __forceinline__ void ldsm4(uint32_t* r, uint32_t addr) {
    asm volatile("ldmatrix.sync.aligned.m8n8.x4.shared.b16 {%0,%1,%2,%3}, [%4];"
                 : "=r"(r[0]), "=r"(r[1]), "=r"(r[2]), "=r"(r[3]) : "r"(addr));
}

__device__ __forceinline__ void ldg_tile(float4* pf, const float* __restrict__ W,
                                         const float* __restrict__ U,
                                         int n0, int n_np, int tid) {
#pragma unroll
    for (int j = 0; j < 4; ++j) {
        int chunk = tid + THREADS * j;        // 0..1023 (16B chunks)
        int row = chunk >> 5, kc = (chunk & 31) << 2;
        int n = n0 + row;
        const float* src = (kc < 64) ? (W + (size_t)n * 64 + kc)
                                     : (U + (size_t)n * 64 + (kc - 64));
        if (n < n_np) pf[j] = *(const float4*)src;
    }
}

__device__ __forceinline__ void cvt_sts(const float4* pf, uint32_t ah_base, int tid) {
#pragma unroll
    for (int j = 0; j < 4; ++j) {
        int chunk = tid + THREADS * j;
        int row = chunk >> 5, kc = (chunk & 31) << 2;
        float4 v = pf[j];
        uint32_t h01 = packh(v.x, v.y), h23 = packh(v.z, v.w);
        __half2 H01 = *(__half2*)&h01, H23 = *(__half2*)&h23;
        uint32_t l01 = packh(v.x - __low2float(H01), v.y - __high2float(H01));
        uint32_t l23 = packh(v.z - __low2float(H23), v.w - __high2float(H23));
        uint32_t d = ah_base + (row * PITCH + kc) * 2;
        asm volatile("st.shared.v2.b32 [%0], {%1,%2};" :: "r"(d), "r"(h01), "r"(h23));
        asm volatile("st.shared.v2.b32 [%0], {%1,%2};"
                     :: "r"(d + AL_DELTA), "r"(l01), "r"(l23));
    }
}

// ---------------------------------------------------------------------------
// Persistent HMMA GEMM, 3 CTAs/SM. Warp layout: 2 m-warps x 4 b-groups of 16.
__global__ __launch_bounds__(THREADS, 3)
void gemm_kernel(const float* __restrict__ W, const float* __restrict__ U,
                 const int* __restrict__ npi, float* __restrict__ V,
                 int n_np, int n_atoms, int n_tiles) {
    extern __shared__ char smem[];
    const uint32_t sb = smem_u32(smem);
    const int tid = threadIdx.x;
    const int wid = tid >> 5, lane = tid & 31;
    const int bg = wid >> 1;                 // b-group: 16 b-cols each
    const int m0 = (wid & 1) * 16;           // warp's row base within 32-row tile
    const int qr = lane >> 2, qc = lane & 3;
    const int r0 = m0 + qr, r1 = r0 + 8;
    int* colsA = (int*)(smem + OFF_COLS);    // [2][32]

    // prologue: X (hi/lo fp16) -> smem
    for (int idx = tid; idx < 4096; idx += THREADS) {
        int b = idx >> 6, kp = (idx & 63) * 2;
        uint32_t d = (b * PITCH + kp) * 2;
        *(uint32_t*)(smem + OFF_XH + d) = ((const uint32_t*)g_Xh)[idx];
        *(uint32_t*)(smem + OFF_XL + d) = ((const uint32_t*)g_Xl)[idx];
    }

    const int bid = blockIdx.x, grid = gridDim.x;
    const int ntl = (n_tiles > bid) ? ((n_tiles - 1 - bid) / grid + 1) : 0;

    if (tid < NTILE && ntl) {
        int n = bid * NTILE + tid;
        colsA[tid] = (n < n_np) ? npi[n] : 0;
    }
    if (bid == 0 && tid < B_DIM)             // V[:,0]; CTA0 rewrites col 0 later in-order
        V[(size_t)tid * n_atoms] = 1.0f + g_hist[0];

    float4 pf[4];
    if (ntl) {
        ldg_tile(pf, W, U, bid * NTILE, n_np, tid);
        cvt_sts(pf, sb + OFF_A, tid);        // buffer 0
    }

    // fragment lane addressing
    const int arow = (lane & 7) + (((lane >> 3) & 1) << 3);
    const int acol = (lane >> 4) << 3;
    const uint32_t Aoff = ((m0 + arow) * PITCH + acol) * 2;
    const int xrow = bg * 16 + (lane & 7) + ((lane >> 4) << 3);
    const int xcol = ((lane >> 3) & 1) << 3;

    for (int i = 0; i < ntl; ++i) {
        const int cur = i & 1, nxt = cur ^ 1;
        const int n0 = (bid + i * grid) * NTILE;
        __syncthreads();                     // S1: buf[cur] + cols[cur] visible

        if (i + 1 < ntl) {
            ldg_tile(pf, W, U, (bid + (i + 1) * grid) * NTILE, n_np, tid);
            if (tid < NTILE) {
                int n = (bid + (i + 1) * grid) * NTILE + tid;
                colsA[nxt * 32 + tid] = (n < n_np) ? npi[n] : 0;
            }
        }
        const int* cols = colsA + cur * 32;
        const int  col0 = cols[r0], col1 = cols[r1];
        const float hv0 = g_hist[col0];
        const float hv1 = g_hist[col1];
        const bool ok0 = (n0 + r0 < n_np), ok1 = (n0 + r1 < n_np);

        const uint32_t AH = sb + OFF_A + cur * ABUF + Aoff;
        float d[2][4] = {};
#pragma unroll
        for (int ks = 0; ks < 8; ++ks) {
            uint32_t ah[4], al[4], bh[4], bl[4];
            ldsm4(ah, AH + ks * 32);
            ldsm4(al, AH + AL_DELTA + ks * 32);
            uint32_t xoff = (xrow * PITCH + ks * 16 + xcol) * 2;
            ldsm4(bh, sb + OFF_XH + xoff);
            ldsm4(bl, sb + OFF_XL + xoff);
            // interleave accumulator chains
            mma16816(d[0], ah, bh[0], bh[1]);
            mma16816(d[1], ah, bh[2], bh[3]);
            mma16816(d[0], al, bh[0], bh[1]);
            mma16816(d[1], al, bh[2], bh[3]);
            mma16816(d[0], ah, bl[0], bl[1]);
            mma16816(d[1], ah, bl[2], bl[3]);
        }

        // epilogue: sigmoid = 0.5 + 0.5*tanh(s/2) + hist, direct scatter.
        // Fixed (nb,j): lanes cover 4 b-rows x 8 consecutive n -> 4 full sectors.
        float* v0 = V + col0;
        float* v1 = V + col1;
#pragma unroll
        for (int nb = 0; nb < 2; ++nb) {
            const size_t boff = (size_t)(bg * 16 + nb * 8 + 2 * qc) * n_atoms;
#pragma unroll
            for (int j = 0; j < 4; ++j) {
                float t;
                asm("tanh.approx.f32 %0, %1;" : "=f"(t) : "f"(0.5f * d[nb][j]));
                float v = fmaf(0.5f, t, 0.5f + ((j >> 1) ? hv1 : hv0));
                size_t a = boff + (size_t)(j & 1) * n_atoms;
                if ((j >> 1) ? ok1 : ok0)
                    ((j >> 1) ? v1 : v0)[a] = v;
            }
        }

        if (i + 1 < ntl)
            cvt_sts(pf, sb + OFF_A + nxt * ABUF, tid);
        // next S1 orders cvt_sts(nxt) before its ldsm readers
    }

    // fused tail: V[b][c] = hist[c] for c in [n_np, n_atoms), grid-strided
    const int total4 = (n_atoms - n_np) >> 2;
    const float4* h4 = (const float4*)(g_hist + n_np);
    for (int t = bid * THREADS + tid; t < B_DIM * total4; t += grid * THREADS) {
        int b = t / total4, c4 = t - b * total4;
        ((float4*)(V + (size_t)b * n_atoms + n_np))[c4] = h4[c4];
    }
}

// ---------------------------------------------------------------------------
// prep: X = [sum_e Z | Q] split to fp16 hi/lo; zero hist.
__global__ void prep_kernel(const float* __restrict__ Z, const float* __restrict__ Q,
                            int n_atoms) {
    if (blockIdx.x < B_DIM) {
        int b = blockIdx.x, k = threadIdx.x;
        if (k < K_DIM) {
            float s;
            if (k < 64) {
                s = 0.f;
#pragma unroll
                for (int e = 0; e < 16; ++e) s += Z[(b * 16 + e) * 64 + k];
            } else {
                s = Q[b * 64 + (k - 64)];
            }
            __half h = __float2half_rn(s);
            g_Xh[b * K_DIM + k] = h;
            g_Xl[b * K_DIM + k] = __float2half_rn(s - __half2float(h));
        }
    } else {
        int idx = (blockIdx.x - B_DIM) * blockDim.x + threadIdx.x;
        int n4 = (n_atoms + 3) >> 2;
        if (idx < n4) ((float4*)g_hist)[idx] = make_float4(0.f, 0.f, 0.f, 0.f);
    }
}

__global__ void hist_kernel(const int* __restrict__ bk, int n_bk) {
    int i = blockIdx.x * blockDim.x + threadIdx.x;
    if (i < n_bk) atomicAdd(&g_hist[bk[i]], 1.0f);
}

// ---------------------------------------------------------------------------
extern "C" void kernel_launch(void* const* d_in, const int* in_sizes, int n_in,
                              void* d_out, int out_size) {
    const float* Z   = (const float*)d_in[0];
    const float* Q   = (const float*)d_in[1];
    const float* W   = (const float*)d_in[2];
    const float* U   = (const float*)d_in[3];
    const int*   npi = (const int*)d_in[4];
    const int*   bk  = (const int*)d_in[5];
    const int n_np    = in_sizes[4];
    const int n_bk    = in_sizes[5];
    const int n_atoms = out_size / B_DIM;
    float* V = (float*)d_out;

    int nsm = 0;
    cudaDeviceGetAttribute(&nsm, cudaDevAttrMultiProcessorCount, 0);
    if (nsm <= 0) nsm = 148;
    cudaFuncSetAttribute(gemm_kernel,
                         cudaFuncAttributeMaxDynamicSharedMemorySize, SMEM_TOTAL);

    int n_tiles = (n_np + NTILE - 1) / NTILE;
    int zb = ((n_atoms + 3) / 4 + 127) / 128;
    prep_kernel<<<B_DIM + zb, 128>>>(Z, Q, n_atoms);
    hist_kernel<<<(n_bk + 255) / 256, 256>>>(bk, n_bk);
    int g = 3 * nsm < n_tiles ? 3 * nsm : n_tiles;
    gemm_kernel<<<g, THREADS, SMEM_TOTAL>>>(W, U, npi, V, n_np, n_atoms, n_tiles);
}

// round 10
// speedup vs baseline: 1.0763x; 1.0763x over previous
#include <cuda_runtime.h>
#include <cuda_fp16.h>
#include <cstdint>

// Shapes fixed by dataset: B=64, E=16, D=64, Q_DIM=64 -> K=128.
#define B_DIM    64
#define K_DIM    128
#define NTILE    32
#define THREADS  256
#define HIST_CAP 262144
#define PITCH    136           // halves per row (272B): ldsm conflict-free
#define ABUF     17408         // Ah+Al per buffer
#define AL_DELTA 8704

// SMEM layout (bytes)
#define OFF_XH   0             // 64 x 136 halves = 17408
#define OFF_XL   17408
#define OFF_A    34816         // [Ah0,Al0][Ah1,Al1] = 2 x 17408
#define OFF_COLS 69632         // 2 x 32 ints
#define SMEM_TOTAL 69888

__device__ __half g_Xh[B_DIM * K_DIM];
__device__ __half g_Xl[B_DIM * K_DIM];
__device__ float  g_hist[HIST_CAP];

// ---------------------------------------------------------------------------
__device__ __forceinline__ uint32_t smem_u32(const void* p) {
    uint32_t a;
    asm("{ .reg .u64 t; cvta.to.shared.u64 t, %1; cvt.u32.u64 %0, t; }"
        : "=r"(a) : "l"(p));
    return a;
}

__device__ __forceinline__ uint32_t packh(float lo, float hi) {
    uint32_t r;
    asm("cvt.rn.f16x2.f32 %0, %1, %2;" : "=r"(r) : "f"(hi), "f"(lo));
    return r;
}

__device__ __forceinline__ void mma16816(float* d, const uint32_t* a,
                                         uint32_t b0, uint32_t b1) {
    asm volatile(
        "mma.sync.aligned.m16n8k16.row.col.f32.f16.f16.f32 "
        "{%0,%1,%2,%3}, {%4,%5,%6,%7}, {%8,%9}, {%0,%1,%2,%3};"
        : "+f"(d[0]), "+f"(d[1]), "+f"(d[2]), "+f"(d[3])
        : "r"(a[0]), "r"(a[1]), "r"(a[2]), "r"(a[3]), "r"(b0), "r"(b1));
}

__device__ __forceinline__ void ldsm4(uint32_t* r, uint32_t addr) {
    asm volatile("ldmatrix.sync.aligned.m8n8.x4.shared.b16 {%0,%1,%2,%3}, [%4];"
                 : "=r"(r[0]), "=r"(r[1]), "=r"(r[2]), "=r"(r[3]) : "r"(addr));
}

__device__ __forceinline__ void ldg_tile(float4* pf, const float* __restrict__ W,
                                         const float* __restrict__ U,
                                         int n0, int n_np, int tid) {
#pragma unroll
    for (int j = 0; j < 4; ++j) {
        int chunk = tid + THREADS * j;        // 0..1023 (16B chunks)
        int row = chunk >> 5, kc = (chunk & 31) << 2;
        int n = n0 + row;
        const float* src = (kc < 64) ? (W + (size_t)n * 64 + kc)
                                     : (U + (size_t)n * 64 + (kc - 64));
        if (n < n_np) pf[j] = *(const float4*)src;
    }
}

__device__ __forceinline__ void cvt_sts(const float4* pf, uint32_t ah_base, int tid) {
#pragma unroll
    for (int j = 0; j < 4; ++j) {
        int chunk = tid + THREADS * j;
        int row = chunk >> 5, kc = (chunk & 31) << 2;
        float4 v = pf[j];
        uint32_t h01 = packh(v.x, v.y), h23 = packh(v.z, v.w);
        __half2 H01 = *(__half2*)&h01, H23 = *(__half2*)&h23;
        uint32_t l01 = packh(v.x - __low2float(H01), v.y - __high2float(H01));
        uint32_t l23 = packh(v.z - __low2float(H23), v.w - __high2float(H23));
        uint32_t d = ah_base + (row * PITCH + kc) * 2;
        asm volatile("st.shared.v2.b32 [%0], {%1,%2};" :: "r"(d), "r"(h01), "r"(h23));
        asm volatile("st.shared.v2.b32 [%0], {%1,%2};"
                     :: "r"(d + AL_DELTA), "r"(l01), "r"(l23));
    }
}

// One tile: hist lookups, MMA from fp16 buf, sigmoid epilogue, direct STG.
__device__ __forceinline__ void compute_tile(
    uint32_t sb, uint32_t AH, const int* cols, int n0,
    int n_np, int n_atoms, float* __restrict__ V,
    int bg, int qc, int r0, int r1, int xrow, int xcol) {

    const int  col0 = cols[r0], col1 = cols[r1];
    const float hv0 = g_hist[col0];
    const float hv1 = g_hist[col1];
    const bool ok0 = (n0 + r0 < n_np), ok1 = (n0 + r1 < n_np);

    float d[2][4] = {};
#pragma unroll
    for (int ks = 0; ks < 8; ++ks) {
        uint32_t ah[4], al[4], bh[4], bl[4];
        ldsm4(ah, AH + ks * 32);
        ldsm4(al, AH + AL_DELTA + ks * 32);
        uint32_t xoff = (xrow * PITCH + ks * 16 + xcol) * 2;
        ldsm4(bh, sb + OFF_XH + xoff);
        ldsm4(bl, sb + OFF_XL + xoff);
        mma16816(d[0], ah, bh[0], bh[1]);
        mma16816(d[1], ah, bh[2], bh[3]);
        mma16816(d[0], al, bh[0], bh[1]);
        mma16816(d[1], al, bh[2], bh[3]);
        mma16816(d[0], ah, bl[0], bl[1]);
        mma16816(d[1], ah, bl[2], bl[3]);
    }

    // sigmoid(s) = 0.5 + 0.5*tanh(s/2) + hist; fixed (nb,j): 4 rows x 8
    // consecutive n per warp-STG -> 4 full 32B sectors (arange indices).
    float* v0 = V + col0;
    float* v1 = V + col1;
#pragma unroll
    for (int nb = 0; nb < 2; ++nb) {
        const size_t boff = (size_t)(bg * 16 + nb * 8 + 2 * qc) * n_atoms;
#pragma unroll
        for (int j = 0; j < 4; ++j) {
            float t;
            asm("tanh.approx.f32 %0, %1;" : "=f"(t) : "f"(0.5f * d[nb][j]));
            float v = fmaf(0.5f, t, 0.5f + ((j >> 1) ? hv1 : hv0));
            size_t a = boff + (size_t)(j & 1) * n_atoms;
            if ((j >> 1) ? ok1 : ok0)
                ((j >> 1) ? v1 : v0)[a] = v;
        }
    }
}

// ---------------------------------------------------------------------------
// Persistent HMMA GEMM, 2 CTAs/SM, DEPTH-2 register prefetch (hand-unrolled x2
// so both pf buffers live in registers; guards are CTA-uniform -> barriers safe).
__global__ __launch_bounds__(THREADS, 2)
void gemm_kernel(const float* __restrict__ W, const float* __restrict__ U,
                 const int* __restrict__ npi, float* __restrict__ V,
                 int n_np, int n_atoms, int n_tiles) {
    extern __shared__ char smem[];
    const uint32_t sb = smem_u32(smem);
    const int tid = threadIdx.x;
    const int wid = tid >> 5, lane = tid & 31;
    const int bg = wid >> 1;                 // 4 b-groups of 16 cols
    const int m0 = (wid & 1) * 16;
    const int qr = lane >> 2, qc = lane & 3;
    const int r0 = m0 + qr, r1 = r0 + 8;
    int* colsA = (int*)(smem + OFF_COLS);    // [2][32]

    // prologue: X (hi/lo fp16) -> smem
    for (int idx = tid; idx < 4096; idx += THREADS) {
        int b = idx >> 6, kp = (idx & 63) * 2;
        uint32_t d = (b * PITCH + kp) * 2;
        *(uint32_t*)(smem + OFF_XH + d) = ((const uint32_t*)g_Xh)[idx];
        *(uint32_t*)(smem + OFF_XL + d) = ((const uint32_t*)g_Xl)[idx];
    }

    const int bid = blockIdx.x, grid = gridDim.x;
    const int ntl = (n_tiles > bid) ? ((n_tiles - 1 - bid) / grid + 1) : 0;

    if (tid < NTILE && ntl) {
        int n = bid * NTILE + tid;
        colsA[tid] = (n < n_np) ? npi[n] : 0;
    }
    if (bid == 0 && tid < B_DIM)             // V[:,0]; CTA0 rewrites col 0 in-order
        V[(size_t)tid * n_atoms] = 1.0f + g_hist[0];

    // fragment lane addressing
    const int arow = (lane & 7) + (((lane >> 3) & 1) << 3);
    const int acol = (lane >> 4) << 3;
    const uint32_t Aoff = ((m0 + arow) * PITCH + acol) * 2;
    const int xrow = bg * 16 + (lane & 7) + ((lane >> 4) << 3);
    const int xcol = ((lane >> 3) & 1) << 3;

    float4 pfA[4], pfB[4];
    if (ntl > 0) ldg_tile(pfA, W, U, bid * NTILE, n_np, tid);
    if (ntl > 1) ldg_tile(pfB, W, U, (bid + grid) * NTILE, n_np, tid);
    if (ntl > 0) cvt_sts(pfA, sb + OFF_A, tid);   // buf 0 <- tile 0

#define TILE_BODY(CUR, PF_LDG, PF_CVT)                                         \
    do {                                                                       \
        const int n0 = (bid + i * grid) * NTILE;                               \
        __syncthreads();  /* buf[CUR]+cols[CUR] ready; buf[CUR^1] free */      \
        if (i + 2 < ntl)                                                       \
            ldg_tile(PF_LDG, W, U, (bid + (i + 2) * grid) * NTILE, n_np, tid); \
        if (i + 1 < ntl && tid < NTILE) {                                      \
            int n = (bid + (i + 1) * grid) * NTILE + tid;                      \
            colsA[((CUR) ^ 1) * 32 + tid] = (n < n_np) ? npi[n] : 0;           \
        }                                                                      \
        compute_tile(sb, sb + OFF_A + (CUR) * ABUF + Aoff,                     \
                     colsA + (CUR) * 32, n0, n_np, n_atoms, V,                 \
                     bg, qc, r0, r1, xrow, xcol);                              \
        if (i + 1 < ntl)                                                       \
            cvt_sts(PF_CVT, sb + OFF_A + ((CUR) ^ 1) * ABUF, tid);             \
    } while (0)

    for (int i = 0; i < ntl;) {
        TILE_BODY(0, pfA, pfB);              // ldg tile i+2 -> pfA; cvt pfB(t i+1)
        ++i;
        if (i < ntl) {
            TILE_BODY(1, pfB, pfA);          // ldg -> pfB; cvt pfA
            ++i;
        }
    }
#undef TILE_BODY

    // fused tail: V[b][c] = hist[c] for c in [n_np, n_atoms), grid-strided
    const int total4 = (n_atoms - n_np) >> 2;
    const float4* h4 = (const float4*)(g_hist + n_np);
    for (int t = bid * THREADS + tid; t < B_DIM * total4; t += grid * THREADS) {
        int b = t / total4, c4 = t - b * total4;
        ((float4*)(V + (size_t)b * n_atoms + n_np))[c4] = h4[c4];
    }
}

// ---------------------------------------------------------------------------
// fused: blocks 0-63 build X (fp16 hi/lo); remaining blocks do bk histogram.
// (g_hist zeroed beforehand via cudaMemsetAsync.)
__global__ void prep_hist_kernel(const float* __restrict__ Z,
                                 const float* __restrict__ Q,
                                 const int* __restrict__ bk, int n_bk) {
    if (blockIdx.x < B_DIM) {
        int b = blockIdx.x, k = threadIdx.x;
        if (k < K_DIM) {
            float s;
            if (k < 64) {
                s = 0.f;
#pragma unroll
                for (int e = 0; e < 16; ++e) s += Z[(b * 16 + e) * 64 + k];
            } else {
                s = Q[b * 64 + (k - 64)];
            }
            __half h = __float2half_rn(s);
            g_Xh[b * K_DIM + k] = h;
            g_Xl[b * K_DIM + k] = __float2half_rn(s - __half2float(h));
        }
    } else {
        int i = (blockIdx.x - B_DIM) * blockDim.x + threadIdx.x;
        if (i < n_bk) atomicAdd(&g_hist[bk[i]], 1.0f);
    }
}

// ---------------------------------------------------------------------------
extern "C" void kernel_launch(void* const* d_in, const int* in_sizes, int n_in,
                              void* d_out, int out_size) {
    const float* Z   = (const float*)d_in[0];
    const float* Q   = (const float*)d_in[1];
    const float* W   = (const float*)d_in[2];
    const float* U   = (const float*)d_in[3];
    const int*   npi = (const int*)d_in[4];
    const int*   bk  = (const int*)d_in[5];
    const int n_np    = in_sizes[4];
    const int n_bk    = in_sizes[5];
    const int n_atoms = out_size / B_DIM;
    float* V = (float*)d_out;

    int nsm = 0;
    cudaDeviceGetAttribute(&nsm, cudaDevAttrMultiProcessorCount, 0);
    if (nsm <= 0) nsm = 148;
    cudaFuncSetAttribute(gemm_kernel,
                         cudaFuncAttributeMaxDynamicSharedMemorySize, SMEM_TOTAL);

    void* hist_ptr = nullptr;
    cudaGetSymbolAddress(&hist_ptr, g_hist);
    cudaMemsetAsync(hist_ptr, 0, (size_t)n_atoms * sizeof(float), 0);

    int hb = (n_bk + 127) / 128;
    prep_hist_kernel<<<B_DIM + hb, 128>>>(Z, Q, bk, n_bk);

    int n_tiles = (n_np + NTILE - 1) / NTILE;
    int g = 2 * nsm < n_tiles ? 2 * nsm : n_tiles;
    gemm_kernel<<<g, THREADS, SMEM_TOTAL>>>(W, U, npi, V, n_np, n_atoms, n_tiles);
}